// round 11
// baseline (speedup 1.0000x reference)
#include <cuda_runtime.h>
#include <cuda_fp16.h>
#include <math.h>
#include <stdint.h>

// Problem constants
#define S_TOK 2048
#define C_DIM 1024
#define E_NUM 16
#define H_DIM 256
#define HS_DIM 2048
#define CAP   2048

// ---------------------------------------------------------------------------
// Device scratch
// ---------------------------------------------------------------------------
__device__ int    g_counts[E_NUM];
__device__ int    g_elist[E_NUM * CAP];
__device__ float  g_wlist[E_NUM * CAP];
__device__ int    g_tok_e[S_TOK * 4];
__device__ int    g_tok_pos[S_TOK * 4];
__device__ __half g_dout_h[(size_t)E_NUM * CAP * C_DIM];
__device__ __half g_xh[(size_t)S_TOK * C_DIM];
__device__ __half g_gate_h[(size_t)E_NUM * H_DIM * C_DIM];   // [e][H][C] K-major
__device__ __half g_up_h[(size_t)E_NUM * H_DIM * C_DIM];
__device__ __half g_down_h[(size_t)E_NUM * C_DIM * H_DIM];   // [e][C][H] K-major
__device__ __half g_sgw_h[(size_t)HS_DIM * C_DIM];
__device__ __half g_suw_h[(size_t)HS_DIM * C_DIM];
__device__ __half g_sdw_h[(size_t)C_DIM * HS_DIM];
__device__ __half g_hidden_h[(size_t)E_NUM * CAP * H_DIM];
__device__ __half g_hs_h[(size_t)S_TOK * HS_DIM];

// ---------------------------------------------------------------------------
// Helpers
// ---------------------------------------------------------------------------
__device__ __forceinline__ uint32_t smem_u32(const void* p) {
    uint32_t a;
    asm("{ .reg .u64 t; cvta.to.shared.u64 t, %1; cvt.u32.u64 %0, t; }" : "=r"(a) : "l"(p));
    return a;
}
__device__ __forceinline__ void cpasync16(uint32_t dst, const void* src) {
    asm volatile("cp.async.cg.shared.global [%0], [%1], 16;" :: "r"(dst), "l"(src));
}
#define CP_COMMIT() asm volatile("cp.async.commit_group;" ::: "memory")
#define CP_WAIT1()  asm volatile("cp.async.wait_group 1;" ::: "memory")
#define CP_WAIT0()  asm volatile("cp.async.wait_group 0;" ::: "memory")
__device__ __forceinline__ void ldsm4(uint32_t* r, uint32_t a) {
    asm volatile("ldmatrix.sync.aligned.m8n8.x4.shared.b16 {%0,%1,%2,%3}, [%4];"
                 : "=r"(r[0]), "=r"(r[1]), "=r"(r[2]), "=r"(r[3]) : "r"(a));
}
__device__ __forceinline__ void mma16(float* d, const uint32_t* a, const uint32_t* b) {
    asm volatile(
        "mma.sync.aligned.m16n8k16.row.col.f32.f16.f16.f32 "
        "{%0,%1,%2,%3}, {%4,%5,%6,%7}, {%8,%9}, {%0,%1,%2,%3};"
        : "+f"(d[0]), "+f"(d[1]), "+f"(d[2]), "+f"(d[3])
        : "r"(a[0]), "r"(a[1]), "r"(a[2]), "r"(a[3]), "r"(b[0]), "r"(b[1]));
}
// swizzled byte offset inside one (rows x 32 halves) stage (row stride 64B)
#define SWZ(row, seg) ((uint32_t)((row) * 64 + ((((seg) ^ ((row) >> 1)) & 3) << 4)))

__device__ __forceinline__ void do_cvt_block(const float* __restrict__ src,
                                             __half* __restrict__ dst,
                                             int lb, int tid) {
    int i = (lb * 256 + tid) * 8;
    float4 a = *(const float4*)(src + i);
    float4 c = *(const float4*)(src + i + 4);
    __half2 h[4];
    h[0] = __floats2half2_rn(a.x, a.y);
    h[1] = __floats2half2_rn(a.z, a.w);
    h[2] = __floats2half2_rn(c.x, c.y);
    h[3] = __floats2half2_rn(c.z, c.w);
    *(uint4*)(dst + i) = *(uint4*)h;
}

// ---------------------------------------------------------------------------
// Prep A: cvt x/sgw/suw, transpose gate/up, router.
// ---------------------------------------------------------------------------
__global__ __launch_bounds__(256)
void prep_kernel(const float* __restrict__ x, const float* __restrict__ sgw,
                 const float* __restrict__ suw,
                 const float* __restrict__ gate_w, const float* __restrict__ up_w,
                 const float* __restrict__ rw, const float* __restrict__ bias,
                 __half* __restrict__ xh, __half* __restrict__ sgw_h,
                 __half* __restrict__ suw_h,
                 __half* __restrict__ gate_h, __half* __restrict__ up_h,
                 int* __restrict__ counts, int* __restrict__ elist,
                 float* __restrict__ wlist, int* __restrict__ tok_e,
                 int* __restrict__ tok_pos) {
    int b = blockIdx.x;
    int tid = threadIdx.x;

    if (b < 3072) {
        const float* src;
        __half* dst;
        int lb;
        if (b < 1024)      { src = x;   dst = xh;    lb = b; }
        else if (b < 2048) { src = sgw; dst = sgw_h; lb = b - 1024; }
        else               { src = suw; dst = suw_h; lb = b - 2048; }
        do_cvt_block(src, dst, lb, tid);
    } else if (b < 11264) {
        __shared__ float t[32][33];
        int tt = b - 3072;
        const float* in;
        __half* outp;
        if (tt < 4096) { in = gate_w; outp = gate_h; }
        else           { in = up_w;   outp = up_h; tt -= 4096; }
        const int R = C_DIM, C = H_DIM;
        int bz = tt >> 8;
        int r = tt & 255;
        int by = r >> 3, bx = r & 7;
        in += (size_t)bz * R * C;
        outp += (size_t)bz * R * C;
        int c0 = bx * 32, r0 = by * 32;
        int tx = tid & 31, ty = tid >> 5;
#pragma unroll
        for (int j = 0; j < 32; j += 8)
            t[ty + j][tx] = in[(size_t)(r0 + ty + j) * C + c0 + tx];
        __syncthreads();
#pragma unroll
        for (int j = 0; j < 32; j += 8)
            outp[(size_t)(c0 + ty + j) * R + r0 + tx] = __float2half_rn(t[tx][ty + j]);
    } else {
        int warp_id = (b - 11264) * 8 + (tid >> 5);
        int lane = tid & 31;
        if (warp_id >= S_TOK) return;
        const float* xr = x + (size_t)warp_id * C_DIM;
        float logits[E_NUM];
#pragma unroll
        for (int e = 0; e < E_NUM; e++) {
            const float* wr = rw + (size_t)e * C_DIM;
            float p = 0.f;
            for (int c = lane; c < C_DIM; c += 32) p = fmaf(xr[c], wr[c], p);
#pragma unroll
            for (int off = 16; off; off >>= 1) p += __shfl_xor_sync(0xffffffffu, p, off);
            logits[e] = p;
        }
        if (lane == 0) {
            float sc[E_NUM], sb[E_NUM];
#pragma unroll
            for (int e = 0; e < E_NUM; e++) {
                sc[e] = 1.f / (1.f + expf(-logits[e]));
                sb[e] = sc[e] + bias[e];
            }
            float gsc[4];
#pragma unroll
            for (int g = 0; g < 4; g++) {
                float m1 = -1e30f, m2 = -1e30f;
#pragma unroll
                for (int j = 0; j < 4; j++) {
                    float v = sb[g * 4 + j];
                    if (v > m1) { m2 = m1; m1 = v; } else if (v > m2) m2 = v;
                }
                gsc[g] = m1 + m2;
            }
            int bg0 = 0;
            for (int g = 1; g < 4; g++) if (gsc[g] > gsc[bg0]) bg0 = g;
            int bg1 = -1;
            for (int g = 0; g < 4; g++) {
                if (g == bg0) continue;
                if (bg1 < 0 || gsc[g] > gsc[bg1]) bg1 = g;
            }
            bool allowed[E_NUM];
#pragma unroll
            for (int e = 0; e < E_NUM; e++) {
                int g = e >> 2;
                allowed[e] = (g == bg0) || (g == bg1);
            }
            int idx[4];
            for (int k = 0; k < 4; k++) {
                int bi = 0; float bv = -1e30f;
                for (int e = 0; e < E_NUM; e++)
                    if (allowed[e] && sb[e] > bv) { bv = sb[e]; bi = e; }
                allowed[bi] = false;
                idx[k] = bi;
            }
            float wsum = 1e-20f;
            for (int k = 0; k < 4; k++) wsum += sc[idx[k]];
            for (int k = 0; k < 4; k++) {
                int e = idx[k];
                int pos = atomicAdd(&counts[e], 1);
                elist[e * CAP + pos] = warp_id;
                wlist[e * CAP + pos] = sc[e] / wsum;
                tok_e[warp_id * 4 + k] = e;
                tok_pos[warp_id * 4 + k] = pos;
            }
        }
    }
}

// ---------------------------------------------------------------------------
// gateup_all: fp16 dual GEMM + SiLU (bids [0,1536)) + overlapped down-weight
// prep (bids [1536,2560): sdw cvt; [2560,6656): down transpose).
// ---------------------------------------------------------------------------
#define GU_SMEM 49152

__global__ __launch_bounds__(256, 2)
void gateup_all(const __half* __restrict__ xh,
                const __half* __restrict__ gate_h, const __half* __restrict__ up_h,
                const __half* __restrict__ sgw_h, const __half* __restrict__ suw_h,
                __half* __restrict__ hidden_h, __half* __restrict__ hs_h,
                const int* __restrict__ counts, const int* __restrict__ elist,
                const float* __restrict__ wlist,
                const float* __restrict__ sdw, __half* __restrict__ sdw_h,
                const float* __restrict__ down_w, __half* __restrict__ down_h) {
    extern __shared__ __align__(16) char sm[];
    int bid = blockIdx.x;
    int tid = threadIdx.x;

    if (bid >= 1536) {
        if (bid < 2560) {
            do_cvt_block(sdw, sdw_h, bid - 1536, tid);
        } else {
            __shared__ float t[32][33];
            int tt = bid - 2560;
            const int R = H_DIM, C = C_DIM;
            int bz = tt >> 8;
            int r = tt & 255;
            int by = r >> 5, bx = r & 31;
            const float* in = down_w + (size_t)bz * R * C;
            __half* outp = down_h + (size_t)bz * R * C;
            int c0 = bx * 32, r0 = by * 32;
            int tx = tid & 31, ty = tid >> 5;
#pragma unroll
            for (int j = 0; j < 32; j += 8)
                t[ty + j][tx] = in[(size_t)(r0 + ty + j) * C + c0 + tx];
            __syncthreads();
#pragma unroll
            for (int j = 0; j < 32; j += 8)
                outp[(size_t)(c0 + ty + j) * R + r0 + tx] = __float2half_rn(t[tx][ty + j]);
        }
        return;
    }

    const int Kd = C_DIM;
    const int NCH = Kd / 32;

    bool routed = bid < 1024;
    int e = 0, cnt = 0, m0, n0;
    const __half* Bg;
    const __half* Bu;
    if (routed) {
        e = bid >> 6;
        int r = bid & 63;
        m0 = (r >> 2) * 128;
        n0 = (r & 3) * 64;
        cnt = counts[e];
        if (m0 >= cnt) return;
        Bg = gate_h + (size_t)e * H_DIM * C_DIM;
        Bu = up_h + (size_t)e * H_DIM * C_DIM;
    } else {
        int t = bid - 1024;
        n0 = (t & 31) * 64;
        m0 = (t >> 5) * 128;
        Bg = sgw_h;
        Bu = suw_h;
    }

    int wid = tid >> 5, lane = tid & 31;
    int grp = lane >> 2, thr = lane & 3;
    int wm = (wid & 3) * 32, wn = (wid >> 2) * 32;   // 4m x 2n

    int lrow = tid >> 2, lseg = tid & 3;
    int atok0, atok1;
    if (routed) {
        int i0 = m0 + lrow, i1 = m0 + lrow + 64;
        atok0 = elist[e * CAP + (i0 < cnt ? i0 : 0)];
        atok1 = elist[e * CAP + (i1 < cnt ? i1 : 0)];
    } else {
        atok0 = m0 + lrow;
        atok1 = m0 + lrow + 64;
    }
    const __half* aptr0 = xh + (size_t)atok0 * Kd + lseg * 8;
    const __half* aptr1 = xh + (size_t)atok1 * Kd + lseg * 8;
    const __half* gptr = Bg + (size_t)(n0 + lrow) * Kd + lseg * 8;
    const __half* uptr = Bu + (size_t)(n0 + lrow) * Kd + lseg * 8;

    uint32_t base = smem_u32(sm);
    uint32_t soA0 = SWZ(lrow, lseg), soA1 = SWZ(lrow + 64, lseg);
    uint32_t soB = SWZ(lrow, lseg);

    int q = lane >> 3;
    int rA0 = wm + (q & 1) * 8 + (lane & 7);
    int sAadd = q >> 1;
    int rB0 = wn + (q >> 1) * 8 + (lane & 7);
    int sBadd = q & 1;

    float accg[2][4][4], accu[2][4][4];
#pragma unroll
    for (int i = 0; i < 2; i++)
#pragma unroll
        for (int j = 0; j < 4; j++)
#pragma unroll
            for (int v = 0; v < 4; v++) { accg[i][j][v] = 0.f; accu[i][j][v] = 0.f; }

#pragma unroll
    for (int p = 0; p < 2; p++) {
        uint32_t sb0 = base + p * 16384;
        int k0 = p * 32;
        cpasync16(sb0 + soA0, aptr0 + k0);
        cpasync16(sb0 + soA1, aptr1 + k0);
        cpasync16(sb0 + 8192 + soB, gptr + k0);
        cpasync16(sb0 + 12288 + soB, uptr + k0);
        CP_COMMIT();
    }

    for (int i = 0; i < NCH; i++) {
        if (i + 1 < NCH) CP_WAIT1(); else CP_WAIT0();
        __syncthreads();
        if (i + 2 < NCH) {
            int s = (i + 2) % 3;
            uint32_t sb0 = base + s * 16384;
            int k0 = (i + 2) * 32;
            cpasync16(sb0 + soA0, aptr0 + k0);
            cpasync16(sb0 + soA1, aptr1 + k0);
            cpasync16(sb0 + 8192 + soB, gptr + k0);
            cpasync16(sb0 + 12288 + soB, uptr + k0);
            CP_COMMIT();
        }
        uint32_t ab = base + (i % 3) * 16384;
        uint32_t gb = ab + 8192;
        uint32_t ub = ab + 12288;
#pragma unroll
        for (int ks = 0; ks < 2; ks++) {
            int s0 = ks * 2;
            uint32_t af[2][4], bgt[2][4], but[2][4];
            ldsm4(af[0], ab + SWZ(rA0, s0 + sAadd));
            ldsm4(af[1], ab + SWZ(rA0 + 16, s0 + sAadd));
            ldsm4(bgt[0], gb + SWZ(rB0, s0 + sBadd));
            ldsm4(bgt[1], gb + SWZ(rB0 + 16, s0 + sBadd));
            ldsm4(but[0], ub + SWZ(rB0, s0 + sBadd));
            ldsm4(but[1], ub + SWZ(rB0 + 16, s0 + sBadd));
#pragma unroll
            for (int mi = 0; mi < 2; mi++)
#pragma unroll
                for (int jj = 0; jj < 4; jj++) {
                    mma16(accg[mi][jj], af[mi], &bgt[jj >> 1][(jj & 1) * 2]);
                    mma16(accu[mi][jj], af[mi], &but[jj >> 1][(jj & 1) * 2]);
                }
        }
    }

#pragma unroll
    for (int mi = 0; mi < 2; mi++) {
#pragma unroll
        for (int half = 0; half < 2; half++) {
            int gidx = m0 + wm + mi * 16 + grp + half * 8;
            float scale = 1.f;
            __half* orow = nullptr;
            bool valid = true;
            if (routed) {
                valid = gidx < cnt;
                if (valid) {
                    scale = wlist[e * CAP + gidx];
                    orow = hidden_h + ((size_t)e * CAP + gidx) * H_DIM + n0;
                }
            } else {
                orow = hs_h + (size_t)gidx * HS_DIM + n0;
            }
            if (valid) {
#pragma unroll
                for (int j = 0; j < 4; j++) {
                    int c = wn + j * 8 + thr * 2;
                    float g0 = accg[mi][j][half * 2], g1 = accg[mi][j][half * 2 + 1];
                    float u0 = accu[mi][j][half * 2], u1 = accu[mi][j][half * 2 + 1];
                    float o0 = (g0 / (1.f + expf(-g0))) * u0 * scale;
                    float o1 = (g1 / (1.f + expf(-g1))) * u1 * scale;
                    *(__half2*)(orow + c) = __floats2half2_rn(o0, o1);
                }
            }
        }
    }
}

// ---------------------------------------------------------------------------
// fp16 down GEMM: tile 128x128, 256 threads, warp tile 32x64, 2 CTAs/SM.
// cp.async 3-stage: A 8KB + B 8KB per stage, 48KB total.
// Shared tiles first (bids [0,128)): K=2048. Routed after (bids [128,2176)),
// 128 tiles per expert (16 m-tiles x 8 n-tiles) covering full CAP.
// ---------------------------------------------------------------------------
#define DN_SMEM 49152

__global__ __launch_bounds__(256, 2)
void down_all(const __half* __restrict__ hidden_h, const __half* __restrict__ down_h,
              const __half* __restrict__ hs_h, const __half* __restrict__ sdw_h,
              __half* __restrict__ dout_h, float* __restrict__ out,
              const int* __restrict__ counts) {
    extern __shared__ __align__(16) char sm[];

    int bid = blockIdx.x;
    bool routed = bid >= 128;
    int e = 0, cnt = 0, m0, n0, Kd;
    const __half* A;
    const __half* B;
    if (routed) {
        int r2 = bid - 128;
        e = r2 >> 7;                 // 128 tiles per expert
        int r = r2 & 127;
        m0 = (r >> 3) * 128;         // 16 m-tiles (full CAP coverage)
        n0 = (r & 7) * 128;          // 8 n-tiles
        cnt = counts[e];
        if (m0 >= cnt) return;
        A = hidden_h + (size_t)e * CAP * H_DIM;
        B = down_h + (size_t)e * C_DIM * H_DIM;
        Kd = H_DIM;
    } else {
        m0 = (bid >> 3) * 128;       // 16 m-tiles
        n0 = (bid & 7) * 128;        // 8 n-tiles
        A = hs_h;
        B = sdw_h;
        Kd = HS_DIM;
    }
    const int NCH = Kd / 32;

    int tid = threadIdx.x, wid = tid >> 5, lane = tid & 31;
    int grp = lane >> 2, thr = lane & 3;
    int wm = (wid & 3) * 32, wn = (wid >> 2) * 64;   // 4m x 2n, warp tile 32x64

    int lrow = tid >> 2, lseg = tid & 3;
    const __half* aptr0 = A + (size_t)(m0 + lrow) * Kd + lseg * 8;
    const __half* aptr1 = A + (size_t)(m0 + lrow + 64) * Kd + lseg * 8;
    const __half* bptr0 = B + (size_t)(n0 + lrow) * Kd + lseg * 8;
    const __half* bptr1 = B + (size_t)(n0 + lrow + 64) * Kd + lseg * 8;

    uint32_t base = smem_u32(sm);
    uint32_t soA0 = SWZ(lrow, lseg), soA1 = SWZ(lrow + 64, lseg);

    int q = lane >> 3;
    int rA0 = wm + (q & 1) * 8 + (lane & 7);
    int sAadd = q >> 1;
    int rB0 = wn + (q >> 1) * 8 + (lane & 7);
    int sBadd = q & 1;

    float acc[2][8][4];
#pragma unroll
    for (int i = 0; i < 2; i++)
#pragma unroll
        for (int j = 0; j < 8; j++)
#pragma unroll
            for (int v = 0; v < 4; v++) acc[i][j][v] = 0.f;

#pragma unroll
    for (int p = 0; p < 2; p++) {
        if (p < NCH) {
            uint32_t sb0 = base + p * 16384;
            int k0 = p * 32;
            cpasync16(sb0 + soA0, aptr0 + k0);
            cpasync16(sb0 + soA1, aptr1 + k0);
            cpasync16(sb0 + 8192 + soA0, bptr0 + k0);
            cpasync16(sb0 + 8192 + soA1, bptr1 + k0);
        }
        CP_COMMIT();
    }

    for (int i = 0; i < NCH; i++) {
        if (i + 1 < NCH) CP_WAIT1(); else CP_WAIT0();
        __syncthreads();
        if (i + 2 < NCH) {
            int s = (i + 2) % 3;
            uint32_t sb0 = base + s * 16384;
            int k0 = (i + 2) * 32;
            cpasync16(sb0 + soA0, aptr0 + k0);
            cpasync16(sb0 + soA1, aptr1 + k0);
            cpasync16(sb0 + 8192 + soA0, bptr0 + k0);
            cpasync16(sb0 + 8192 + soA1, bptr1 + k0);
            CP_COMMIT();
        }
        uint32_t ab = base + (i % 3) * 16384;
        uint32_t bb = ab + 8192;
#pragma unroll
        for (int ks = 0; ks < 2; ks++) {
            int s0 = ks * 2;
            uint32_t af[2][4], bft[4][4];
            ldsm4(af[0], ab + SWZ(rA0, s0 + sAadd));
            ldsm4(af[1], ab + SWZ(rA0 + 16, s0 + sAadd));
#pragma unroll
            for (int tb = 0; tb < 4; tb++)
                ldsm4(bft[tb], bb + SWZ(rB0 + tb * 16, s0 + sBadd));
#pragma unroll
            for (int mi = 0; mi < 2; mi++)
#pragma unroll
                for (int jj = 0; jj < 8; jj++)
                    mma16(acc[mi][jj], af[mi], &bft[jj >> 1][(jj & 1) * 2]);
        }
    }

#pragma unroll
    for (int mi = 0; mi < 2; mi++) {
#pragma unroll
        for (int half = 0; half < 2; half++) {
            int gidx = m0 + wm + mi * 16 + grp + half * 8;
            if (routed) {
                if (gidx < cnt) {
                    __half* orow = dout_h + ((size_t)e * CAP + gidx) * C_DIM + n0;
#pragma unroll
                    for (int j = 0; j < 8; j++) {
                        int c = wn + j * 8 + thr * 2;
                        *(__half2*)(orow + c) = __floats2half2_rn(acc[mi][j][half * 2],
                                                                  acc[mi][j][half * 2 + 1]);
                    }
                }
            } else {
                float* orow = out + (size_t)gidx * C_DIM + n0;
#pragma unroll
                for (int j = 0; j < 8; j++) {
                    int c = wn + j * 8 + thr * 2;
                    float2 o;
                    o.x = acc[mi][j][half * 2];
                    o.y = acc[mi][j][half * 2 + 1];
                    *(float2*)(orow + c) = o;
                }
            }
        }
    }
}

// ---------------------------------------------------------------------------
// Final combine: out[s] += sum_k dout_h[e_k][pos_k]
// ---------------------------------------------------------------------------
__global__ void combine_kernel(const int* __restrict__ tok_e,
                               const int* __restrict__ tok_pos,
                               const __half* __restrict__ dout_h,
                               float* __restrict__ out) {
    int s = blockIdx.x;
    int c = threadIdx.x * 4;
    float4 acc = *(const float4*)(out + (size_t)s * C_DIM + c);
#pragma unroll
    for (int k = 0; k < 4; k++) {
        int e = tok_e[s * 4 + k];
        int p = tok_pos[s * 4 + k];
        const __half* row = dout_h + ((size_t)e * CAP + p) * C_DIM + c;
        uint2 raw = *(const uint2*)row;
        __half2 h0 = *(__half2*)&raw.x;
        __half2 h1 = *(__half2*)&raw.y;
        float2 f0 = __half22float2(h0);
        float2 f1 = __half22float2(h1);
        acc.x += f0.x; acc.y += f0.y; acc.z += f1.x; acc.w += f1.y;
    }
    *(float4*)(out + (size_t)s * C_DIM + c) = acc;
}

// ---------------------------------------------------------------------------
// Launch
// ---------------------------------------------------------------------------
extern "C" void kernel_launch(void* const* d_in, const int* in_sizes, int n_in,
                              void* d_out, int out_size) {
    const float* x      = (const float*)d_in[0];
    const float* rw     = (const float*)d_in[1];
    const float* bias   = (const float*)d_in[2];
    const float* gate_w = (const float*)d_in[3];
    const float* up_w   = (const float*)d_in[4];
    const float* down_w = (const float*)d_in[5];
    const float* sgw    = (const float*)d_in[6];
    const float* suw    = (const float*)d_in[7];
    const float* sdw    = (const float*)d_in[8];
    float* out = (float*)d_out;

    int *counts, *elist, *tok_e, *tok_pos;
    float *wlist;
    __half *xh, *gate_h, *up_h, *down_h, *sgw_h, *suw_h, *sdw_h, *hidden_h, *hs_h, *dout_h;
    cudaGetSymbolAddress((void**)&counts, g_counts);
    cudaGetSymbolAddress((void**)&elist, g_elist);
    cudaGetSymbolAddress((void**)&wlist, g_wlist);
    cudaGetSymbolAddress((void**)&tok_e, g_tok_e);
    cudaGetSymbolAddress((void**)&tok_pos, g_tok_pos);
    cudaGetSymbolAddress((void**)&dout_h, g_dout_h);
    cudaGetSymbolAddress((void**)&xh, g_xh);
    cudaGetSymbolAddress((void**)&gate_h, g_gate_h);
    cudaGetSymbolAddress((void**)&up_h, g_up_h);
    cudaGetSymbolAddress((void**)&down_h, g_down_h);
    cudaGetSymbolAddress((void**)&sgw_h, g_sgw_h);
    cudaGetSymbolAddress((void**)&suw_h, g_suw_h);
    cudaGetSymbolAddress((void**)&sdw_h, g_sdw_h);
    cudaGetSymbolAddress((void**)&hidden_h, g_hidden_h);
    cudaGetSymbolAddress((void**)&hs_h, g_hs_h);

    cudaFuncSetAttribute(gateup_all, cudaFuncAttributeMaxDynamicSharedMemorySize, GU_SMEM);
    cudaFuncSetAttribute(down_all, cudaFuncAttributeMaxDynamicSharedMemorySize, DN_SMEM);

    cudaMemsetAsync(counts, 0, E_NUM * sizeof(int));

    // Prep A: x/sgw/suw cvt + gate/up transpose + router
    prep_kernel<<<11520, 256>>>(x, sgw, suw, gate_w, up_w, rw, bias,
                                xh, sgw_h, suw_h, gate_h, up_h,
                                counts, elist, wlist, tok_e, tok_pos);

    // gateup GEMM (1536 blocks) + overlapped down-weight prep (5120 blocks)
    gateup_all<<<6656, 256, GU_SMEM>>>(xh, gate_h, up_h, sgw_h, suw_h,
                                       hidden_h, hs_h, counts, elist, wlist,
                                       sdw, sdw_h, down_w, down_h);

    // down GEMM: shared-first (128) + routed (2048, full CAP coverage), 128x128 tiles
    down_all<<<2176, 256, DN_SMEM>>>(hidden_h, down_h, hs_h, sdw_h, dout_h, out, counts);

    // Combine routed rows into out
    combine_kernel<<<S_TOK, 256>>>(tok_e, tok_pos, dout_h, out);
}

// round 13
// speedup vs baseline: 1.0360x; 1.0360x over previous
#include <cuda_runtime.h>
#include <cuda_fp16.h>
#include <math.h>
#include <stdint.h>

// Problem constants
#define S_TOK 2048
#define C_DIM 1024
#define E_NUM 16
#define H_DIM 256
#define HS_DIM 2048
#define CAP   2048

// ---------------------------------------------------------------------------
// Device scratch
// ---------------------------------------------------------------------------
__device__ int    g_counts[E_NUM];
__device__ int    g_elist[E_NUM * CAP];
__device__ float  g_wlist[E_NUM * CAP];
__device__ int    g_tok_e[S_TOK * 4];
__device__ int    g_tok_pos[S_TOK * 4];
__device__ __half g_dout_h[(size_t)E_NUM * CAP * C_DIM];
__device__ __half g_xh[(size_t)S_TOK * C_DIM];
__device__ __half g_gate_h[(size_t)E_NUM * H_DIM * C_DIM];   // [e][H][C] K-major
__device__ __half g_up_h[(size_t)E_NUM * H_DIM * C_DIM];
__device__ __half g_down_h[(size_t)E_NUM * C_DIM * H_DIM];   // [e][C][H] K-major
__device__ __half g_sgw_h[(size_t)HS_DIM * C_DIM];
__device__ __half g_suw_h[(size_t)HS_DIM * C_DIM];
__device__ __half g_sdw_h[(size_t)C_DIM * HS_DIM];
__device__ __half g_hidden_h[(size_t)E_NUM * CAP * H_DIM];
__device__ __half g_hs_h[(size_t)S_TOK * HS_DIM];

// ---------------------------------------------------------------------------
// Helpers
// ---------------------------------------------------------------------------
__device__ __forceinline__ uint32_t smem_u32(const void* p) {
    uint32_t a;
    asm("{ .reg .u64 t; cvta.to.shared.u64 t, %1; cvt.u32.u64 %0, t; }" : "=r"(a) : "l"(p));
    return a;
}
__device__ __forceinline__ void cpasync16(uint32_t dst, const void* src) {
    asm volatile("cp.async.cg.shared.global [%0], [%1], 16;" :: "r"(dst), "l"(src));
}
#define CP_COMMIT() asm volatile("cp.async.commit_group;" ::: "memory")
#define CP_WAIT1()  asm volatile("cp.async.wait_group 1;" ::: "memory")
#define CP_WAIT0()  asm volatile("cp.async.wait_group 0;" ::: "memory")
__device__ __forceinline__ void ldsm4(uint32_t* r, uint32_t a) {
    asm volatile("ldmatrix.sync.aligned.m8n8.x4.shared.b16 {%0,%1,%2,%3}, [%4];"
                 : "=r"(r[0]), "=r"(r[1]), "=r"(r[2]), "=r"(r[3]) : "r"(a));
}
__device__ __forceinline__ void mma16(float* d, const uint32_t* a, const uint32_t* b) {
    asm volatile(
        "mma.sync.aligned.m16n8k16.row.col.f32.f16.f16.f32 "
        "{%0,%1,%2,%3}, {%4,%5,%6,%7}, {%8,%9}, {%0,%1,%2,%3};"
        : "+f"(d[0]), "+f"(d[1]), "+f"(d[2]), "+f"(d[3])
        : "r"(a[0]), "r"(a[1]), "r"(a[2]), "r"(a[3]), "r"(b[0]), "r"(b[1]));
}
// swizzled byte offset inside one (rows x 32 halves) stage (row stride 64B)
#define SWZ(row, seg) ((uint32_t)((row) * 64 + ((((seg) ^ ((row) >> 1)) & 3) << 4)))

__device__ __forceinline__ void do_cvt_block(const float* __restrict__ src,
                                             __half* __restrict__ dst,
                                             int lb, int tid) {
    int i = (lb * 256 + tid) * 8;
    float4 a = *(const float4*)(src + i);
    float4 c = *(const float4*)(src + i + 4);
    __half2 h[4];
    h[0] = __floats2half2_rn(a.x, a.y);
    h[1] = __floats2half2_rn(a.z, a.w);
    h[2] = __floats2half2_rn(c.x, c.y);
    h[3] = __floats2half2_rn(c.z, c.w);
    *(uint4*)(dst + i) = *(uint4*)h;
}

// ---------------------------------------------------------------------------
// Prep A: cvt sgw/suw, transpose gate/up, router (+fused x cvt).
// blocks [0,2048): cvt sgw/suw; [2048,10240): transpose; [10240,10496): router
// ---------------------------------------------------------------------------
__global__ __launch_bounds__(256)
void prep_kernel(const float* __restrict__ x, const float* __restrict__ sgw,
                 const float* __restrict__ suw,
                 const float* __restrict__ gate_w, const float* __restrict__ up_w,
                 const float* __restrict__ rw, const float* __restrict__ bias,
                 __half* __restrict__ xh, __half* __restrict__ sgw_h,
                 __half* __restrict__ suw_h,
                 __half* __restrict__ gate_h, __half* __restrict__ up_h,
                 int* __restrict__ counts, int* __restrict__ elist,
                 float* __restrict__ wlist, int* __restrict__ tok_e,
                 int* __restrict__ tok_pos) {
    int b = blockIdx.x;
    int tid = threadIdx.x;

    if (b < 2048) {
        const float* src;
        __half* dst;
        int lb;
        if (b < 1024) { src = sgw; dst = sgw_h; lb = b; }
        else          { src = suw; dst = suw_h; lb = b - 1024; }
        do_cvt_block(src, dst, lb, tid);
    } else if (b < 10240) {
        __shared__ float t[32][33];
        int tt = b - 2048;
        const float* in;
        __half* outp;
        if (tt < 4096) { in = gate_w; outp = gate_h; }
        else           { in = up_w;   outp = up_h; tt -= 4096; }
        const int R = C_DIM, C = H_DIM;
        int bz = tt >> 8;
        int r = tt & 255;
        int by = r >> 3, bx = r & 7;
        in += (size_t)bz * R * C;
        outp += (size_t)bz * R * C;
        int c0 = bx * 32, r0 = by * 32;
        int tx = tid & 31, ty = tid >> 5;
#pragma unroll
        for (int j = 0; j < 32; j += 8)
            t[ty + j][tx] = in[(size_t)(r0 + ty + j) * C + c0 + tx];
        __syncthreads();
#pragma unroll
        for (int j = 0; j < 32; j += 8)
            outp[(size_t)(c0 + ty + j) * R + r0 + tx] = __float2half_rn(t[tx][ty + j]);
    } else {
        // ---- router block: 8 tokens per block; also cvt those 8 x-rows to fp16
        int tok0 = (b - 10240) * 8;
        {
            const float* xs = x + (size_t)tok0 * C_DIM;
            __half* xd = xh + (size_t)tok0 * C_DIM;
#pragma unroll
            for (int it = 0; it < 4; it++) {
                int i = (it * 256 + tid) * 8;
                float4 a = *(const float4*)(xs + i);
                float4 c = *(const float4*)(xs + i + 4);
                __half2 h[4];
                h[0] = __floats2half2_rn(a.x, a.y);
                h[1] = __floats2half2_rn(a.z, a.w);
                h[2] = __floats2half2_rn(c.x, c.y);
                h[3] = __floats2half2_rn(c.z, c.w);
                *(uint4*)(xd + i) = *(uint4*)h;
            }
        }
        int warp_id = tok0 + (tid >> 5);
        int lane = tid & 31;
        if (warp_id >= S_TOK) return;
        const float* xr = x + (size_t)warp_id * C_DIM;
        float logits[E_NUM];
#pragma unroll
        for (int e = 0; e < E_NUM; e++) {
            const float* wr = rw + (size_t)e * C_DIM;
            float p = 0.f;
            for (int c = lane; c < C_DIM; c += 32) p = fmaf(xr[c], wr[c], p);
#pragma unroll
            for (int off = 16; off; off >>= 1) p += __shfl_xor_sync(0xffffffffu, p, off);
            logits[e] = p;
        }
        if (lane == 0) {
            float sc[E_NUM], sb[E_NUM];
#pragma unroll
            for (int e = 0; e < E_NUM; e++) {
                sc[e] = 1.f / (1.f + expf(-logits[e]));
                sb[e] = sc[e] + bias[e];
            }
            float gsc[4];
#pragma unroll
            for (int g = 0; g < 4; g++) {
                float m1 = -1e30f, m2 = -1e30f;
#pragma unroll
                for (int j = 0; j < 4; j++) {
                    float v = sb[g * 4 + j];
                    if (v > m1) { m2 = m1; m1 = v; } else if (v > m2) m2 = v;
                }
                gsc[g] = m1 + m2;
            }
            int bg0 = 0;
            for (int g = 1; g < 4; g++) if (gsc[g] > gsc[bg0]) bg0 = g;
            int bg1 = -1;
            for (int g = 0; g < 4; g++) {
                if (g == bg0) continue;
                if (bg1 < 0 || gsc[g] > gsc[bg1]) bg1 = g;
            }
            bool allowed[E_NUM];
#pragma unroll
            for (int e = 0; e < E_NUM; e++) {
                int g = e >> 2;
                allowed[e] = (g == bg0) || (g == bg1);
            }
            int idx[4];
            for (int k = 0; k < 4; k++) {
                int bi = 0; float bv = -1e30f;
                for (int e = 0; e < E_NUM; e++)
                    if (allowed[e] && sb[e] > bv) { bv = sb[e]; bi = e; }
                allowed[bi] = false;
                idx[k] = bi;
            }
            float wsum = 1e-20f;
            for (int k = 0; k < 4; k++) wsum += sc[idx[k]];
            for (int k = 0; k < 4; k++) {
                int e = idx[k];
                int pos = atomicAdd(&counts[e], 1);
                elist[e * CAP + pos] = warp_id;
                wlist[e * CAP + pos] = sc[e] / wsum;
                tok_e[warp_id * 4 + k] = e;
                tok_pos[warp_id * 4 + k] = pos;
            }
        }
    }
}

// ---------------------------------------------------------------------------
// gateup_all: fp16 dual GEMM + SiLU (bids [0,1536)) + overlapped down-weight
// prep (bids [1536,2560): sdw cvt; [2560,6656): down transpose).
// GEMM: 256 thr, tile 128x64, 2 CTAs/SM, cp.async 3-stage.
// ---------------------------------------------------------------------------
#define GU_SMEM 49152

__global__ __launch_bounds__(256, 2)
void gateup_all(const __half* __restrict__ xh,
                const __half* __restrict__ gate_h, const __half* __restrict__ up_h,
                const __half* __restrict__ sgw_h, const __half* __restrict__ suw_h,
                __half* __restrict__ hidden_h, __half* __restrict__ hs_h,
                const int* __restrict__ counts, const int* __restrict__ elist,
                const float* __restrict__ wlist,
                const float* __restrict__ sdw, __half* __restrict__ sdw_h,
                const float* __restrict__ down_w, __half* __restrict__ down_h) {
    extern __shared__ __align__(16) char sm[];
    int bid = blockIdx.x;
    int tid = threadIdx.x;

    if (bid >= 1536) {
        if (bid < 2560) {
            do_cvt_block(sdw, sdw_h, bid - 1536, tid);
        } else {
            __shared__ float t[32][33];
            int tt = bid - 2560;
            const int R = H_DIM, C = C_DIM;
            int bz = tt >> 8;
            int r = tt & 255;
            int by = r >> 5, bx = r & 31;
            const float* in = down_w + (size_t)bz * R * C;
            __half* outp = down_h + (size_t)bz * R * C;
            int c0 = bx * 32, r0 = by * 32;
            int tx = tid & 31, ty = tid >> 5;
#pragma unroll
            for (int j = 0; j < 32; j += 8)
                t[ty + j][tx] = in[(size_t)(r0 + ty + j) * C + c0 + tx];
            __syncthreads();
#pragma unroll
            for (int j = 0; j < 32; j += 8)
                outp[(size_t)(c0 + ty + j) * R + r0 + tx] = __float2half_rn(t[tx][ty + j]);
        }
        return;
    }

    const int Kd = C_DIM;
    const int NCH = Kd / 32;

    bool routed = bid < 1024;
    int e = 0, cnt = 0, m0, n0;
    const __half* Bg;
    const __half* Bu;
    if (routed) {
        e = bid >> 6;
        int r = bid & 63;
        m0 = (r >> 2) * 128;
        n0 = (r & 3) * 64;
        cnt = counts[e];
        if (m0 >= cnt) return;
        Bg = gate_h + (size_t)e * H_DIM * C_DIM;
        Bu = up_h + (size_t)e * H_DIM * C_DIM;
    } else {
        int t = bid - 1024;
        n0 = (t & 31) * 64;
        m0 = (t >> 5) * 128;
        Bg = sgw_h;
        Bu = suw_h;
    }

    int wid = tid >> 5, lane = tid & 31;
    int grp = lane >> 2, thr = lane & 3;
    int wm = (wid & 3) * 32, wn = (wid >> 2) * 32;   // 4m x 2n

    int lrow = tid >> 2, lseg = tid & 3;
    int atok0, atok1;
    if (routed) {
        int i0 = m0 + lrow, i1 = m0 + lrow + 64;
        atok0 = elist[e * CAP + (i0 < cnt ? i0 : 0)];
        atok1 = elist[e * CAP + (i1 < cnt ? i1 : 0)];
    } else {
        atok0 = m0 + lrow;
        atok1 = m0 + lrow + 64;
    }
    const __half* aptr0 = xh + (size_t)atok0 * Kd + lseg * 8;
    const __half* aptr1 = xh + (size_t)atok1 * Kd + lseg * 8;
    const __half* gptr = Bg + (size_t)(n0 + lrow) * Kd + lseg * 8;
    const __half* uptr = Bu + (size_t)(n0 + lrow) * Kd + lseg * 8;

    uint32_t base = smem_u32(sm);
    uint32_t soA0 = SWZ(lrow, lseg), soA1 = SWZ(lrow + 64, lseg);
    uint32_t soB = SWZ(lrow, lseg);

    int q = lane >> 3;
    int rA0 = wm + (q & 1) * 8 + (lane & 7);
    int sAadd = q >> 1;
    int rB0 = wn + (q >> 1) * 8 + (lane & 7);
    int sBadd = q & 1;

    float accg[2][4][4], accu[2][4][4];
#pragma unroll
    for (int i = 0; i < 2; i++)
#pragma unroll
        for (int j = 0; j < 4; j++)
#pragma unroll
            for (int v = 0; v < 4; v++) { accg[i][j][v] = 0.f; accu[i][j][v] = 0.f; }

#pragma unroll
    for (int p = 0; p < 2; p++) {
        uint32_t sb0 = base + p * 16384;
        int k0 = p * 32;
        cpasync16(sb0 + soA0, aptr0 + k0);
        cpasync16(sb0 + soA1, aptr1 + k0);
        cpasync16(sb0 + 8192 + soB, gptr + k0);
        cpasync16(sb0 + 12288 + soB, uptr + k0);
        CP_COMMIT();
    }

    for (int i = 0; i < NCH; i++) {
        if (i + 1 < NCH) CP_WAIT1(); else CP_WAIT0();
        __syncthreads();
        if (i + 2 < NCH) {
            int s = (i + 2) % 3;
            uint32_t sb0 = base + s * 16384;
            int k0 = (i + 2) * 32;
            cpasync16(sb0 + soA0, aptr0 + k0);
            cpasync16(sb0 + soA1, aptr1 + k0);
            cpasync16(sb0 + 8192 + soB, gptr + k0);
            cpasync16(sb0 + 12288 + soB, uptr + k0);
            CP_COMMIT();
        }
        uint32_t ab = base + (i % 3) * 16384;
        uint32_t gb = ab + 8192;
        uint32_t ub = ab + 12288;
#pragma unroll
        for (int ks = 0; ks < 2; ks++) {
            int s0 = ks * 2;
            uint32_t af[2][4], bgt[2][4], but[2][4];
            ldsm4(af[0], ab + SWZ(rA0, s0 + sAadd));
            ldsm4(af[1], ab + SWZ(rA0 + 16, s0 + sAadd));
            ldsm4(bgt[0], gb + SWZ(rB0, s0 + sBadd));
            ldsm4(bgt[1], gb + SWZ(rB0 + 16, s0 + sBadd));
            ldsm4(but[0], ub + SWZ(rB0, s0 + sBadd));
            ldsm4(but[1], ub + SWZ(rB0 + 16, s0 + sBadd));
#pragma unroll
            for (int mi = 0; mi < 2; mi++)
#pragma unroll
                for (int jj = 0; jj < 4; jj++) {
                    mma16(accg[mi][jj], af[mi], &bgt[jj >> 1][(jj & 1) * 2]);
                    mma16(accu[mi][jj], af[mi], &but[jj >> 1][(jj & 1) * 2]);
                }
        }
    }

#pragma unroll
    for (int mi = 0; mi < 2; mi++) {
#pragma unroll
        for (int half = 0; half < 2; half++) {
            int gidx = m0 + wm + mi * 16 + grp + half * 8;
            float scale = 1.f;
            __half* orow = nullptr;
            bool valid = true;
            if (routed) {
                valid = gidx < cnt;
                if (valid) {
                    scale = wlist[e * CAP + gidx];
                    orow = hidden_h + ((size_t)e * CAP + gidx) * H_DIM + n0;
                }
            } else {
                orow = hs_h + (size_t)gidx * HS_DIM + n0;
            }
            if (valid) {
#pragma unroll
                for (int j = 0; j < 4; j++) {
                    int c = wn + j * 8 + thr * 2;
                    float g0 = accg[mi][j][half * 2], g1 = accg[mi][j][half * 2 + 1];
                    float u0 = accu[mi][j][half * 2], u1 = accu[mi][j][half * 2 + 1];
                    float o0 = (g0 / (1.f + expf(-g0))) * u0 * scale;
                    float o1 = (g1 / (1.f + expf(-g1))) * u1 * scale;
                    *(__half2*)(orow + c) = __floats2half2_rn(o0, o1);
                }
            }
        }
    }
}

// ---------------------------------------------------------------------------
// fp16 down GEMM (round-9 proven geometry): tile 128x64, 256 threads,
// 2 CTAs/SM, cp.async 3-stage (A 8KB + B 4KB per stage, 36KB total).
// Shared tiles first (bids [0,256)), routed after (bids [256,4352)).
// ---------------------------------------------------------------------------
#define DN_SMEM 36864

__global__ __launch_bounds__(256, 2)
void down_all(const __half* __restrict__ hidden_h, const __half* __restrict__ down_h,
              const __half* __restrict__ hs_h, const __half* __restrict__ sdw_h,
              __half* __restrict__ dout_h, float* __restrict__ out,
              const int* __restrict__ counts) {
    extern __shared__ __align__(16) char sm[];

    int bid = blockIdx.x;
    bool routed = bid >= 256;
    int e = 0, cnt = 0, m0, n0, Kd;
    const __half* A;
    const __half* B;
    if (routed) {
        int r2 = bid - 256;
        e = r2 >> 8;
        int r = r2 & 255;
        m0 = (r >> 4) * 128;
        n0 = (r & 15) * 64;
        cnt = counts[e];
        if (m0 >= cnt) return;
        A = hidden_h + (size_t)e * CAP * H_DIM;
        B = down_h + (size_t)e * C_DIM * H_DIM;
        Kd = H_DIM;
    } else {
        m0 = (bid >> 4) * 128;
        n0 = (bid & 15) * 64;
        A = hs_h;
        B = sdw_h;
        Kd = HS_DIM;
    }
    const int NCH = Kd / 32;

    int tid = threadIdx.x, wid = tid >> 5, lane = tid & 31;
    int grp = lane >> 2, thr = lane & 3;
    int wm = (wid & 3) * 32, wn = (wid >> 2) * 32;

    int lrow = tid >> 2, lseg = tid & 3;
    const __half* aptr0 = A + (size_t)(m0 + lrow) * Kd + lseg * 8;
    const __half* aptr1 = A + (size_t)(m0 + lrow + 64) * Kd + lseg * 8;
    const __half* bptr = B + (size_t)(n0 + lrow) * Kd + lseg * 8;

    uint32_t base = smem_u32(sm);
    uint32_t soA0 = SWZ(lrow, lseg), soA1 = SWZ(lrow + 64, lseg);
    uint32_t soB = SWZ(lrow, lseg);

    int q = lane >> 3;
    int rA0 = wm + (q & 1) * 8 + (lane & 7);
    int sAadd = q >> 1;
    int rB0 = wn + (q >> 1) * 8 + (lane & 7);
    int sBadd = q & 1;

    float acc[2][4][4];
#pragma unroll
    for (int i = 0; i < 2; i++)
#pragma unroll
        for (int j = 0; j < 4; j++)
#pragma unroll
            for (int v = 0; v < 4; v++) acc[i][j][v] = 0.f;

#pragma unroll
    for (int p = 0; p < 2; p++) {
        if (p < NCH) {
            uint32_t sb0 = base + p * 12288;
            int k0 = p * 32;
            cpasync16(sb0 + soA0, aptr0 + k0);
            cpasync16(sb0 + soA1, aptr1 + k0);
            cpasync16(sb0 + 8192 + soB, bptr + k0);
        }
        CP_COMMIT();
    }

    for (int i = 0; i < NCH; i++) {
        if (i + 1 < NCH) CP_WAIT1(); else CP_WAIT0();
        __syncthreads();
        if (i + 2 < NCH) {
            int s = (i + 2) % 3;
            uint32_t sb0 = base + s * 12288;
            int k0 = (i + 2) * 32;
            cpasync16(sb0 + soA0, aptr0 + k0);
            cpasync16(sb0 + soA1, aptr1 + k0);
            cpasync16(sb0 + 8192 + soB, bptr + k0);
            CP_COMMIT();
        }
        uint32_t ab = base + (i % 3) * 12288;
        uint32_t bb = ab + 8192;
#pragma unroll
        for (int ks = 0; ks < 2; ks++) {
            int s0 = ks * 2;
            uint32_t af[2][4], bft[2][4];
            ldsm4(af[0], ab + SWZ(rA0, s0 + sAadd));
            ldsm4(af[1], ab + SWZ(rA0 + 16, s0 + sAadd));
            ldsm4(bft[0], bb + SWZ(rB0, s0 + sBadd));
            ldsm4(bft[1], bb + SWZ(rB0 + 16, s0 + sBadd));
#pragma unroll
            for (int mi = 0; mi < 2; mi++)
#pragma unroll
                for (int jj = 0; jj < 4; jj++)
                    mma16(acc[mi][jj], af[mi], &bft[jj >> 1][(jj & 1) * 2]);
        }
    }

#pragma unroll
    for (int mi = 0; mi < 2; mi++) {
#pragma unroll
        for (int half = 0; half < 2; half++) {
            int gidx = m0 + wm + mi * 16 + grp + half * 8;
            if (routed) {
                if (gidx < cnt) {
                    __half* orow = dout_h + ((size_t)e * CAP + gidx) * C_DIM + n0;
#pragma unroll
                    for (int j = 0; j < 4; j++) {
                        int c = wn + j * 8 + thr * 2;
                        *(__half2*)(orow + c) = __floats2half2_rn(acc[mi][j][half * 2],
                                                                  acc[mi][j][half * 2 + 1]);
                    }
                }
            } else {
                float* orow = out + (size_t)gidx * C_DIM + n0;
#pragma unroll
                for (int j = 0; j < 4; j++) {
                    int c = wn + j * 8 + thr * 2;
                    float2 o;
                    o.x = acc[mi][j][half * 2];
                    o.y = acc[mi][j][half * 2 + 1];
                    *(float2*)(orow + c) = o;
                }
            }
        }
    }
}

// ---------------------------------------------------------------------------
// Final combine: out[s] += sum_k dout_h[e_k][pos_k]
// ---------------------------------------------------------------------------
__global__ void combine_kernel(const int* __restrict__ tok_e,
                               const int* __restrict__ tok_pos,
                               const __half* __restrict__ dout_h,
                               float* __restrict__ out) {
    int s = blockIdx.x;
    int c = threadIdx.x * 4;
    float4 acc = *(const float4*)(out + (size_t)s * C_DIM + c);
#pragma unroll
    for (int k = 0; k < 4; k++) {
        int e = tok_e[s * 4 + k];
        int p = tok_pos[s * 4 + k];
        const __half* row = dout_h + ((size_t)e * CAP + p) * C_DIM + c;
        uint2 raw = *(const uint2*)row;
        __half2 h0 = *(__half2*)&raw.x;
        __half2 h1 = *(__half2*)&raw.y;
        float2 f0 = __half22float2(h0);
        float2 f1 = __half22float2(h1);
        acc.x += f0.x; acc.y += f0.y; acc.z += f1.x; acc.w += f1.y;
    }
    *(float4*)(out + (size_t)s * C_DIM + c) = acc;
}

// ---------------------------------------------------------------------------
// Launch
// ---------------------------------------------------------------------------
extern "C" void kernel_launch(void* const* d_in, const int* in_sizes, int n_in,
                              void* d_out, int out_size) {
    const float* x      = (const float*)d_in[0];
    const float* rw     = (const float*)d_in[1];
    const float* bias   = (const float*)d_in[2];
    const float* gate_w = (const float*)d_in[3];
    const float* up_w   = (const float*)d_in[4];
    const float* down_w = (const float*)d_in[5];
    const float* sgw    = (const float*)d_in[6];
    const float* suw    = (const float*)d_in[7];
    const float* sdw    = (const float*)d_in[8];
    float* out = (float*)d_out;

    int *counts, *elist, *tok_e, *tok_pos;
    float *wlist;
    __half *xh, *gate_h, *up_h, *down_h, *sgw_h, *suw_h, *sdw_h, *hidden_h, *hs_h, *dout_h;
    cudaGetSymbolAddress((void**)&counts, g_counts);
    cudaGetSymbolAddress((void**)&elist, g_elist);
    cudaGetSymbolAddress((void**)&wlist, g_wlist);
    cudaGetSymbolAddress((void**)&tok_e, g_tok_e);
    cudaGetSymbolAddress((void**)&tok_pos, g_tok_pos);
    cudaGetSymbolAddress((void**)&dout_h, g_dout_h);
    cudaGetSymbolAddress((void**)&xh, g_xh);
    cudaGetSymbolAddress((void**)&gate_h, g_gate_h);
    cudaGetSymbolAddress((void**)&up_h, g_up_h);
    cudaGetSymbolAddress((void**)&down_h, g_down_h);
    cudaGetSymbolAddress((void**)&sgw_h, g_sgw_h);
    cudaGetSymbolAddress((void**)&suw_h, g_suw_h);
    cudaGetSymbolAddress((void**)&sdw_h, g_sdw_h);
    cudaGetSymbolAddress((void**)&hidden_h, g_hidden_h);
    cudaGetSymbolAddress((void**)&hs_h, g_hs_h);

    cudaFuncSetAttribute(gateup_all, cudaFuncAttributeMaxDynamicSharedMemorySize, GU_SMEM);
    cudaFuncSetAttribute(down_all, cudaFuncAttributeMaxDynamicSharedMemorySize, DN_SMEM);

    cudaMemsetAsync(counts, 0, E_NUM * sizeof(int));

    // Prep A: sgw/suw cvt + gate/up transpose + router (with fused x cvt)
    prep_kernel<<<10496, 256>>>(x, sgw, suw, gate_w, up_w, rw, bias,
                                xh, sgw_h, suw_h, gate_h, up_h,
                                counts, elist, wlist, tok_e, tok_pos);

    // gateup GEMM (1536 blocks) + overlapped down-weight prep (5120 blocks)
    gateup_all<<<6656, 256, GU_SMEM>>>(xh, gate_h, up_h, sgw_h, suw_h,
                                       hidden_h, hs_h, counts, elist, wlist,
                                       sdw, sdw_h, down_w, down_h);

    // down GEMM: shared-first (256) + routed (4096), 128x64 tiles
    down_all<<<4352, 256, DN_SMEM>>>(hidden_h, down_h, hs_h, sdw_h, dout_h, out, counts);

    // Combine routed rows into out
    combine_kernel<<<S_TOK, 256>>>(tok_e, tok_pos, dout_h, out);
}